// round 5
// baseline (speedup 1.0000x reference)
#include <cuda_runtime.h>
#include <math.h>

#define B_  4
#define S_  2048
#define D_  512
#define H_  8
#define DK_ 64

// Scratch (no cudaMalloc allowed)
__device__ float g_Qh[(size_t)B_ * H_ * S_ * DK_];
__device__ float g_Kh[(size_t)B_ * H_ * S_ * DK_];
__device__ float g_Vh[(size_t)B_ * H_ * S_ * DK_];
__device__ float g_ctx[(size_t)B_ * S_ * D_];

// ---------------- tf32 mma helpers (m16n8k8, row.col) ----------------
__device__ __forceinline__ unsigned f2tf(float f) {
    unsigned u;
    asm("cvt.rna.tf32.f32 %0, %1;" : "=r"(u) : "f"(f));
    return u;
}
__device__ __forceinline__ void mma_tf32(float* d, const unsigned* a, unsigned b0, unsigned b1) {
    asm("mma.sync.aligned.m16n8k8.row.col.f32.tf32.tf32.f32 "
        "{%0,%1,%2,%3},{%4,%5,%6,%7},{%8,%9},{%0,%1,%2,%3};"
        : "+f"(d[0]), "+f"(d[1]), "+f"(d[2]), "+f"(d[3])
        : "r"(a[0]), "r"(a[1]), "r"(a[2]), "r"(a[3]), "r"(b0), "r"(b1));
}
// ldmatrix on tf32 data: one m8n8.b16 tile (8 rows x 16B) delivers to lane l
// the 32-bit element (row l>>2, tf32col l&3) == native mma fragment layout.
__device__ __forceinline__ void ldsm_x4(unsigned* r, unsigned saddr) {
    asm volatile("ldmatrix.sync.aligned.m8n8.x4.shared.b16 {%0,%1,%2,%3}, [%4];"
        : "=r"(r[0]), "=r"(r[1]), "=r"(r[2]), "=r"(r[3]) : "r"(saddr));
}
// Fragment layouts (lane = 4*g + t):
//  A(16x8): a0=(g,t) a1=(g+8,t) a2=(g,t+4) a3=(g+8,t+4)   [row, kcol]
//  B(8x8, col-major): b0=(t, g) b1=(t+4, g)               [krow, ncol]
//  C(16x8): c0=(g,2t) c1=(g,2t+1) c2=(g+8,2t) c3=(g+8,2t+1)

// ---------------- Projection GEMM: C = A @ W^T + bias --------------------
// CTA 128x128, BK=32, 256 threads = 8 warps (4m x 2n), warp tile 32x64.
#define GST 36
__global__ void __launch_bounds__(256) gemm_tf32(const float* __restrict__ A,
                                                 const float* __restrict__ W,
                                                 const float* __restrict__ bias,
                                                 float* __restrict__ C, int mode)
{
    __shared__ unsigned As[128 * GST];
    __shared__ unsigned Bs[128 * GST];
    const int tid = threadIdx.x;
    const int warp = tid >> 5, lane = tid & 31;
    const int g = lane >> 2, t = lane & 3;
    const int wm = (warp & 3) * 32;
    const int wn = (warp >> 2) * 64;
    const int m0 = blockIdx.y * 128;
    const int n0 = blockIdx.x * 128;

    const unsigned sA = (unsigned)__cvta_generic_to_shared(As);
    const unsigned sB = (unsigned)__cvta_generic_to_shared(Bs);
    // LDSM address bases (per-lane)
    const unsigned aAddr = sA + (((wm + (lane & 15)) * GST + ((lane >> 4) << 2)) << 2);
    const unsigned bAddr = sB + (((wn + (lane & 7) + ((lane >> 4) << 3)) * GST
                                  + (((lane >> 3) & 1) << 2)) << 2);

    float acc[2][8][4];
#pragma unroll
    for (int mt = 0; mt < 2; mt++)
#pragma unroll
        for (int nt = 0; nt < 8; nt++)
#pragma unroll
            for (int i = 0; i < 4; i++) acc[mt][nt][i] = 0.f;

    for (int k0 = 0; k0 < 512; k0 += 32) {
        __syncthreads();
#pragma unroll
        for (int it = 0; it < 4; it++) {
            const int slot = tid + it * 256;
            const int row = slot >> 3, c4 = (slot & 7) << 2;
            const float4 av = *(const float4*)(A + (size_t)(m0 + row) * 512 + k0 + c4);
            uint4 ua = make_uint4(f2tf(av.x), f2tf(av.y), f2tf(av.z), f2tf(av.w));
            *(uint4*)&As[row * GST + c4] = ua;
            const float4 bv = *(const float4*)(W + (size_t)(n0 + row) * 512 + k0 + c4);
            uint4 ub = make_uint4(f2tf(bv.x), f2tf(bv.y), f2tf(bv.z), f2tf(bv.w));
            *(uint4*)&Bs[row * GST + c4] = ub;
        }
        __syncthreads();
#pragma unroll
        for (int kk = 0; kk < 32; kk += 8) {
            unsigned af[2][4];
            ldsm_x4(af[0], aAddr + (kk << 2));
            ldsm_x4(af[1], aAddr + ((16 * GST + kk) << 2));
#pragma unroll
            for (int nt2 = 0; nt2 < 4; nt2++) {
                unsigned bw[4];
                ldsm_x4(bw, bAddr + ((nt2 * 16 * GST + kk) << 2));
                mma_tf32(acc[0][2 * nt2],     af[0], bw[0], bw[1]);
                mma_tf32(acc[0][2 * nt2 + 1], af[0], bw[2], bw[3]);
                mma_tf32(acc[1][2 * nt2],     af[1], bw[0], bw[1]);
                mma_tf32(acc[1][2 * nt2 + 1], af[1], bw[2], bw[3]);
            }
        }
    }

#pragma unroll
    for (int mt = 0; mt < 2; mt++) {
        const int r = m0 + wm + mt * 16 + g;
#pragma unroll
        for (int nt = 0; nt < 8; nt++) {
            const int c = n0 + wn + nt * 8 + 2 * t;
            const float bb0 = bias[c], bb1 = bias[c + 1];
            const float2 v0 = make_float2(acc[mt][nt][0] + bb0, acc[mt][nt][1] + bb1);
            const float2 v1 = make_float2(acc[mt][nt][2] + bb0, acc[mt][nt][3] + bb1);
            size_t i0, i1;
            if (mode == 0) {
                const int b = r >> 11, s = r & 2047;
                const int h = c >> 6, dk = c & 63;
                i0 = ((size_t)(b * H_ + h) * S_ + s) * DK_ + dk;
                const int s1 = (r + 8) & 2047, b1r = (r + 8) >> 11;
                i1 = ((size_t)(b1r * H_ + h) * S_ + s1) * DK_ + dk;
            } else {
                i0 = (size_t)r * 512 + c;
                i1 = (size_t)(r + 8) * 512 + c;
            }
            *(float2*)(C + i0) = v0;
            *(float2*)(C + i1) = v1;
        }
    }
}

// ---------------- Flash attention, tf32 tensor-core + LDSM ----------------
// CTA = (b, h, 64-row q tile), 4 warps. K tile = 64.
// Q,K: [row][dk] stride 68. V: TRANSPOSED [dk][key] stride 68 (LDSM-friendly).
// smem = 3 * 64*68*4 = 52224 B -> 4 CTAs/SM.
#define QST 68
#define KST 68
#define VTST 68
#define OFF_K (64 * QST)
#define OFF_V (OFF_K + 64 * KST)
#define SMEM_WORDS (OFF_V + 64 * VTST)

// exp2-domain scale: 1/H * log2(e)
#define QSCALE (0.125f * 1.44269504088896340736f)

__global__ void __launch_bounds__(128, 4) attn_tf32(const float* __restrict__ Qh,
                                                    const float* __restrict__ Kh,
                                                    const float* __restrict__ Vh,
                                                    const int* __restrict__ mask,
                                                    float* __restrict__ ctx)
{
    extern __shared__ unsigned sh[];
    unsigned* Qs = sh;
    unsigned* Ks = sh + OFF_K;
    unsigned* Vt = sh + OFF_V;

    const int tid = threadIdx.x;
    const int w = tid >> 5, lane = tid & 31;
    const int g = lane >> 2, t = lane & 3;
    const int q0 = blockIdx.x * 64;
    const int h = blockIdx.y;
    const int b = blockIdx.z;
    const size_t head = (size_t)(b * H_ + h);

    const unsigned sQ = (unsigned)__cvta_generic_to_shared(Qs);
    const unsigned sK = (unsigned)__cvta_generic_to_shared(Ks);
    const unsigned sV = (unsigned)__cvta_generic_to_shared(Vt);
    // LDSM per-lane address bases
    const unsigned aqAddr = sQ + (((w * 16 + (lane & 15)) * QST + ((lane >> 4) << 2)) << 2);
    const unsigned bkAddr = sK + ((((lane & 7) + ((lane >> 4) << 3)) * KST
                                   + (((lane >> 3) & 1) << 2)) << 2);
    const unsigned bvAddr = sV + ((((lane & 7) + ((lane >> 4) << 3)) * VTST
                                   + (((lane >> 3) & 1) << 2)) << 2);

    // Load Q tile; fold 1/H * log2(e) into Q (scores land in exp2 domain).
    const float* Qg = Qh + (head * S_ + q0) * DK_;
    for (int slot = tid; slot < 1024; slot += 128) {
        const int row = slot >> 4, c4 = (slot & 15) << 2;
        const float4 qv = *(const float4*)(Qg + row * 64 + c4);
        uint4 uq = make_uint4(f2tf(qv.x * QSCALE), f2tf(qv.y * QSCALE),
                              f2tf(qv.z * QSCALE), f2tf(qv.w * QSCALE));
        *(uint4*)&Qs[row * QST + c4] = uq;
    }

    float acc[8][4];
#pragma unroll
    for (int nt = 0; nt < 8; nt++)
#pragma unroll
        for (int i = 0; i < 4; i++) acc[nt][i] = 0.f;
    float mrow0 = -INFINITY, mrow1 = -INFINITY;
    float lrow0 = 0.f, lrow1 = 0.f;

    const int r0g = q0 + w * 16 + g;
    const int r1g = r0g + 8;
    const int* maskb = mask + (size_t)b * S_ * S_;
    const int sbase = lane & 28;
    const int src0 = sbase | (t >> 1);
    const int src2 = sbase | ((t >> 1) + 2);

    for (int kt = 0; kt < S_ / 64; kt++) {
        const int k0 = kt * 64;
        const float* Kg = Kh + (head * S_ + k0) * DK_;
        const float* Vg = Vh + (head * S_ + k0) * DK_;
        __syncthreads();   // previous iter done reading Ks/Vt
        // K: [key][dk], STS.128
        for (int slot = tid; slot < 1024; slot += 128) {
            const int row = slot >> 4, c4 = (slot & 15) << 2;
            const float4 kv = *(const float4*)(Kg + row * 64 + c4);
            uint4 uk = make_uint4(f2tf(kv.x), f2tf(kv.y), f2tf(kv.z), f2tf(kv.w));
            *(uint4*)&Ks[row * KST + c4] = uk;
        }
        // V: transposed store Vt[dk][key]; key-major lane map -> conflict-free STS
        for (int slot = tid; slot < 1024; slot += 128) {
            const int key = slot & 63, c4 = (slot >> 6) << 2;
            const float4 vv = *(const float4*)(Vg + key * 64 + c4);
            Vt[(c4 + 0) * VTST + key] = f2tf(vv.x);
            Vt[(c4 + 1) * VTST + key] = f2tf(vv.y);
            Vt[(c4 + 2) * VTST + key] = f2tf(vv.z);
            Vt[(c4 + 3) * VTST + key] = f2tf(vv.w);
        }
        __syncthreads();

        // ---- S = (Q*scale) @ K^T  (16x64 per warp), LDSM fragments ----
        float sc[8][4];
#pragma unroll
        for (int nt = 0; nt < 8; nt++)
#pragma unroll
            for (int i = 0; i < 4; i++) sc[nt][i] = 0.f;

#pragma unroll
        for (int kk = 0; kk < 64; kk += 8) {
            unsigned aq[4];
            ldsm_x4(aq, aqAddr + (kk << 2));
#pragma unroll
            for (int nt2 = 0; nt2 < 4; nt2++) {
                unsigned bk[4];
                ldsm_x4(bk, bkAddr + ((nt2 * 16 * KST + kk) << 2));
                mma_tf32(sc[2 * nt2],     aq, bk[0], bk[1]);
                mma_tf32(sc[2 * nt2 + 1], aq, bk[2], bk[3]);
            }
        }

        // ---- mask ----
#pragma unroll
        for (int nt = 0; nt < 8; nt++) {
            const int kc = k0 + nt * 8 + 2 * t;
            const int2 m0v = *(const int2*)(maskb + (size_t)r0g * S_ + kc);
            const int2 m1v = *(const int2*)(maskb + (size_t)r1g * S_ + kc);
            sc[nt][0] = m0v.x ? sc[nt][0] : -1e9f;
            sc[nt][1] = m0v.y ? sc[nt][1] : -1e9f;
            sc[nt][2] = m1v.x ? sc[nt][2] : -1e9f;
            sc[nt][3] = m1v.y ? sc[nt][3] : -1e9f;
        }

        // ---- online softmax in exp2 domain ----
        float mt0 = -INFINITY, mt1 = -INFINITY;
#pragma unroll
        for (int nt = 0; nt < 8; nt++) {
            mt0 = fmaxf(mt0, fmaxf(sc[nt][0], sc[nt][1]));
            mt1 = fmaxf(mt1, fmaxf(sc[nt][2], sc[nt][3]));
        }
        mt0 = fmaxf(mt0, __shfl_xor_sync(0xffffffffu, mt0, 1));
        mt0 = fmaxf(mt0, __shfl_xor_sync(0xffffffffu, mt0, 2));
        mt1 = fmaxf(mt1, __shfl_xor_sync(0xffffffffu, mt1, 1));
        mt1 = fmaxf(mt1, __shfl_xor_sync(0xffffffffu, mt1, 2));
        const float mn0 = fmaxf(mrow0, mt0), mn1 = fmaxf(mrow1, mt1);
        const float al0 = exp2f(mrow0 - mn0), al1 = exp2f(mrow1 - mn1);
        mrow0 = mn0; mrow1 = mn1;
        float ps0 = 0.f, ps1 = 0.f;
#pragma unroll
        for (int nt = 0; nt < 8; nt++) {
            sc[nt][0] = exp2f(sc[nt][0] - mn0);
            sc[nt][1] = exp2f(sc[nt][1] - mn0);
            sc[nt][2] = exp2f(sc[nt][2] - mn1);
            sc[nt][3] = exp2f(sc[nt][3] - mn1);
            ps0 += sc[nt][0] + sc[nt][1];
            ps1 += sc[nt][2] + sc[nt][3];
        }
        ps0 += __shfl_xor_sync(0xffffffffu, ps0, 1);
        ps0 += __shfl_xor_sync(0xffffffffu, ps0, 2);
        ps1 += __shfl_xor_sync(0xffffffffu, ps1, 1);
        ps1 += __shfl_xor_sync(0xffffffffu, ps1, 2);
        lrow0 = lrow0 * al0 + ps0;
        lrow1 = lrow1 * al1 + ps1;
#pragma unroll
        for (int nt = 0; nt < 8; nt++) {
            acc[nt][0] *= al0; acc[nt][1] *= al0;
            acc[nt][2] *= al1; acc[nt][3] *= al1;
        }

        // ---- acc += P @ V ; P A-frags via in-quad shuffles, V via LDSM ----
#pragma unroll
        for (int s = 0; s < 8; s++) {
            const unsigned u0 = f2tf(sc[s][0]);
            const unsigned u1 = f2tf(sc[s][1]);
            const unsigned u2 = f2tf(sc[s][2]);
            const unsigned u3 = f2tf(sc[s][3]);
            unsigned ap[4];
            const unsigned v00 = __shfl_sync(0xffffffffu, u0, src0);
            const unsigned v01 = __shfl_sync(0xffffffffu, u1, src0);
            ap[0] = (t & 1) ? v01 : v00;
            const unsigned v20 = __shfl_sync(0xffffffffu, u2, src0);
            const unsigned v21 = __shfl_sync(0xffffffffu, u3, src0);
            ap[1] = (t & 1) ? v21 : v20;
            const unsigned w00 = __shfl_sync(0xffffffffu, u0, src2);
            const unsigned w01 = __shfl_sync(0xffffffffu, u1, src2);
            ap[2] = (t & 1) ? w01 : w00;
            const unsigned w20 = __shfl_sync(0xffffffffu, u2, src2);
            const unsigned w21 = __shfl_sync(0xffffffffu, u3, src2);
            ap[3] = (t & 1) ? w21 : w20;

            const int kk = s * 8;
#pragma unroll
            for (int nt2 = 0; nt2 < 4; nt2++) {
                unsigned bv[4];
                ldsm_x4(bv, bvAddr + ((nt2 * 16 * VTST + kk) << 2));
                mma_tf32(acc[2 * nt2],     ap, bv[0], bv[1]);
                mma_tf32(acc[2 * nt2 + 1], ap, bv[2], bv[3]);
            }
        }
    }

    // ---- normalize + write ctx [B,S,H,DK] ----
    const float inv0 = 1.f / lrow0, inv1 = 1.f / lrow1;
#pragma unroll
    for (int nt = 0; nt < 8; nt++) {
        const int dk = nt * 8 + 2 * t;
        const size_t i0 = ((size_t)(b * S_ + r0g) * H_ + h) * DK_ + dk;
        const size_t i1 = ((size_t)(b * S_ + r1g) * H_ + h) * DK_ + dk;
        *(float2*)(ctx + i0) = make_float2(acc[nt][0] * inv0, acc[nt][1] * inv0);
        *(float2*)(ctx + i1) = make_float2(acc[nt][2] * inv1, acc[nt][3] * inv1);
    }
}

extern "C" void kernel_launch(void* const* d_in, const int* in_sizes, int n_in,
                              void* d_out, int out_size)
{
    (void)in_sizes; (void)n_in; (void)out_size;
    const float* q   = (const float*)d_in[0];
    const float* k   = (const float*)d_in[1];
    const float* v   = (const float*)d_in[2];
    const int*  mask = (const int*)d_in[3];
    const float* Wq  = (const float*)d_in[4];
    const float* bq  = (const float*)d_in[5];
    const float* Wk  = (const float*)d_in[6];
    const float* bk  = (const float*)d_in[7];
    const float* Wv  = (const float*)d_in[8];
    const float* bv  = (const float*)d_in[9];
    const float* Wo  = (const float*)d_in[10];
    const float* bo  = (const float*)d_in[11];
    float* out = (float*)d_out;

    float *Qh, *Kh, *Vh, *ctx;
    cudaGetSymbolAddress((void**)&Qh,  g_Qh);
    cudaGetSymbolAddress((void**)&Kh,  g_Kh);
    cudaGetSymbolAddress((void**)&Vh,  g_Vh);
    cudaGetSymbolAddress((void**)&ctx, g_ctx);

    const dim3 gg(4, 64), bb(256);
    gemm_tf32<<<gg, bb>>>(q, Wq, bq, Qh, 0);
    gemm_tf32<<<gg, bb>>>(k, Wk, bk, Kh, 0);
    gemm_tf32<<<gg, bb>>>(v, Wv, bv, Vh, 0);

    const int shmem = SMEM_WORDS * sizeof(unsigned);   // 52224 B
    cudaFuncSetAttribute(attn_tf32, cudaFuncAttributeMaxDynamicSharedMemorySize, shmem);
    attn_tf32<<<dim3(32, 8, 4), 128, shmem>>>(Qh, Kh, Vh, mask, ctx);

    gemm_tf32<<<gg, bb>>>(ctx, Wo, bo, out, 1);
}